// round 1
// baseline (speedup 1.0000x reference)
#include <cuda_runtime.h>

#define B_   2
#define N_   2048
#define DIM_ 768
#define H_   12
#define DH_  64
#define M1   (B_*N_)     // 4096
#define NC1  (3*DIM_)    // 2304

// ---- scratch (device globals: allocation-free contract) ----
__device__ float g_xq[M1*DIM_];
__device__ float g_wqkv[NC1*DIM_];
__device__ float g_bqkv[NC1];
__device__ float g_wp[DIM_*DIM_];
__device__ float g_bp[DIM_];
__device__ float g_q[B_*H_*N_*DH_];
__device__ float g_k[B_*H_*N_*DH_];
__device__ float g_v[B_*H_*N_*DH_];
__device__ float g_z[M1*DIM_];

// ---- fixed-point quantizers (rintf = round-half-even, matches jnp.round) ----
__device__ __forceinline__ float qf(float x, float s, float inv, float lo, float hi) {
    float r = rintf(x * s);
    r = fminf(fmaxf(r, lo), hi);
    return r * inv;
}
__device__ __forceinline__ float q16_8(float x)  { return qf(x, 256.f, 0.00390625f, -32768.f, 32767.f); }
__device__ __forceinline__ float q32_16(float x) { return qf(x, 65536.f, 1.52587890625e-5f, -2.147483648e9f, 2.147483647e9f); }
__device__ __forceinline__ float q32_8(float x)  { return qf(x, 256.f, 0.00390625f, -2.147483648e9f, 2.147483647e9f); }

// ---- kernel 1: quantize all inputs into scratch ----
__global__ void quantize_all(const float* __restrict__ x, const float* __restrict__ wqkv,
                             const float* __restrict__ bqkv, const float* __restrict__ wp,
                             const float* __restrict__ bp) {
    long i = (long)blockIdx.x * blockDim.x + threadIdx.x;
    const long NX  = (long)M1 * DIM_;     // 3145728
    const long NW1 = (long)NC1 * DIM_;    // 1769472
    const long NW2 = (long)DIM_ * DIM_;   // 589824
    if (i < NX)  { g_xq[i]  = q32_16(x[i]);  return; }
    i -= NX;
    if (i < NW1) { g_wqkv[i] = q16_8(wqkv[i]); return; }
    i -= NW1;
    if (i < NW2) { g_wp[i]   = q16_8(wp[i]);   return; }
    i -= NW2;
    if (i < NC1) { g_bqkv[i] = q16_8(bqkv[i]); return; }
    i -= NC1;
    if (i < DIM_){ g_bp[i]   = q16_8(bp[i]); }
}

// ---- kernel 2: QKV projection GEMM: C[4096,2304] = Xq * Wqkv^T (+bias, quant, scatter) ----
__global__ void __launch_bounds__(256) gemm_qkv() {
    __shared__ float As[16][132];
    __shared__ float Bs[16][132];
    const int tid = threadIdx.x;
    const int m0 = blockIdx.y * 128;
    const int n0 = blockIdx.x * 128;
    const int tr = (tid >> 4) << 3;   // 0..120 row base
    const int tc = (tid & 15) << 3;   // 0..120 col base
    const int lr = tid >> 2;          // 0..63
    const int lc = (tid & 3) << 2;    // 0,4,8,12

    float acc[8][8];
    #pragma unroll
    for (int i = 0; i < 8; i++)
        #pragma unroll
        for (int j = 0; j < 8; j++) acc[i][j] = 0.f;

    const float* Ag = g_xq   + (long)(m0 + lr) * DIM_ + lc;
    const float* Bg = g_wqkv + (long)(n0 + lr) * DIM_ + lc;

    for (int k0 = 0; k0 < DIM_; k0 += 16) {
        float4 a0 = *(const float4*)(Ag + k0);
        float4 a1 = *(const float4*)(Ag + 64 * DIM_ + k0);
        float4 b0 = *(const float4*)(Bg + k0);
        float4 b1 = *(const float4*)(Bg + 64 * DIM_ + k0);
        __syncthreads();
        As[lc+0][lr] = a0.x; As[lc+1][lr] = a0.y; As[lc+2][lr] = a0.z; As[lc+3][lr] = a0.w;
        As[lc+0][lr+64] = a1.x; As[lc+1][lr+64] = a1.y; As[lc+2][lr+64] = a1.z; As[lc+3][lr+64] = a1.w;
        Bs[lc+0][lr] = b0.x; Bs[lc+1][lr] = b0.y; Bs[lc+2][lr] = b0.z; Bs[lc+3][lr] = b0.w;
        Bs[lc+0][lr+64] = b1.x; Bs[lc+1][lr+64] = b1.y; Bs[lc+2][lr+64] = b1.z; Bs[lc+3][lr+64] = b1.w;
        __syncthreads();
        #pragma unroll
        for (int kk = 0; kk < 16; kk++) {
            float a[8], b[8];
            #pragma unroll
            for (int i = 0; i < 8; i++) a[i] = As[kk][tr + i];
            #pragma unroll
            for (int j = 0; j < 8; j++) b[j] = Bs[kk][tc + j];
            #pragma unroll
            for (int i = 0; i < 8; i++)
                #pragma unroll
                for (int j = 0; j < 8; j++) acc[i][j] = fmaf(a[i], b[j], acc[i][j]);
        }
    }
    // epilogue: bias + (16,8) quant + scatter to per-head q/k/v [B,H,N,DH]
    #pragma unroll
    for (int j = 0; j < 8; j++) {
        int n = n0 + tc + j;
        float bias = g_bqkv[n];
        int h = n / 192;
        int rr = n - h * 192;
        int seg = rr >> 6;
        int e = rr & 63;
        float* dst = (seg == 0) ? g_q : ((seg == 1) ? g_k : g_v);
        #pragma unroll
        for (int i = 0; i < 8; i++) {
            int m = m0 + tr + i;
            int bi = m >> 11, nr = m & 2047;
            dst[(((long)(bi * H_ + h) * N_ + nr) * DH_) + e] = q16_8(acc[i][j] + bias);
        }
    }
}

// ---- kernel 3: fused attention: per CTA one (b,h) and a 128-row q tile ----
// s = q16_8(q @ k^T) tile-by-tile; z += s @ v; z never leaves registers until quantized.
__global__ void __launch_bounds__(256) attn_kernel() {
    extern __shared__ float sm[];
    float* q_s = sm;               // [64][128]   transposed (e-major)
    float* kv  = sm + 64 * 128;    // k phase: [64][128]; v phase: [128][68]
    float* s_s = kv + 8704;        // [128][129]

    const int tid = threadIdx.x;
    const int bh = blockIdx.y;
    const int q0 = blockIdx.x * 128;
    const float* qb = g_q + (long)bh * N_ * DH_;
    const float* kb = g_k + (long)bh * N_ * DH_;
    const float* vb = g_v + (long)bh * N_ * DH_;

    const int f4 = (tid & 15) << 2;  // 0..60 step 4
    const int r0 = tid >> 4;         // 0..15

    // load q tile transposed
    #pragma unroll
    for (int p = 0; p < 8; p++) {
        int r = r0 + p * 16;
        float4 v4 = *(const float4*)(qb + (long)(q0 + r) * DH_ + f4);
        q_s[(f4 + 0) * 128 + r] = v4.x;
        q_s[(f4 + 1) * 128 + r] = v4.y;
        q_s[(f4 + 2) * 128 + r] = v4.z;
        q_s[(f4 + 3) * 128 + r] = v4.w;
    }

    const int tr = (tid >> 4) << 3;  // 8-row group
    const int tc = (tid & 15) << 3;  // 8-col group (phase 1)
    const int zc = (tid & 15) << 2;  // 4-col group (phase 2, e dim)

    float zacc[8][4];
    #pragma unroll
    for (int i = 0; i < 8; i++)
        #pragma unroll
        for (int j = 0; j < 4; j++) zacc[i][j] = 0.f;

    for (int kt = 0; kt < 16; kt++) {
        const int kbase = kt * 128;
        __syncthreads();  // prior phase-2 done reading kv
        // load k tile transposed
        #pragma unroll
        for (int p = 0; p < 8; p++) {
            int r = r0 + p * 16;
            float4 v4 = *(const float4*)(kb + (long)(kbase + r) * DH_ + f4);
            kv[(f4 + 0) * 128 + r] = v4.x;
            kv[(f4 + 1) * 128 + r] = v4.y;
            kv[(f4 + 2) * 128 + r] = v4.z;
            kv[(f4 + 3) * 128 + r] = v4.w;
        }
        __syncthreads();

        // phase 1: s = q @ k^T (128x128, K=64)
        float sacc[8][8];
        #pragma unroll
        for (int i = 0; i < 8; i++)
            #pragma unroll
            for (int j = 0; j < 8; j++) sacc[i][j] = 0.f;
        #pragma unroll 4
        for (int e = 0; e < 64; e++) {
            float a[8], b[8];
            #pragma unroll
            for (int i = 0; i < 8; i++) a[i] = q_s[e * 128 + tr + i];
            #pragma unroll
            for (int j = 0; j < 8; j++) b[j] = kv[e * 128 + tc + j];
            #pragma unroll
            for (int i = 0; i < 8; i++)
                #pragma unroll
                for (int j = 0; j < 8; j++) sacc[i][j] = fmaf(a[i], b[j], sacc[i][j]);
        }
        // quantize s (16,8) into smem
        #pragma unroll
        for (int i = 0; i < 8; i++)
            #pragma unroll
            for (int j = 0; j < 8; j++)
                s_s[(tr + i) * 129 + (tc + j)] = q16_8(sacc[i][j]);
        __syncthreads();

        // load v tile row-major, pitch 68
        #pragma unroll
        for (int p = 0; p < 8; p++) {
            int r = r0 + p * 16;
            float4 v4 = *(const float4*)(vb + (long)(kbase + r) * DH_ + f4);
            *(float4*)&kv[r * 68 + f4] = v4;
        }
        __syncthreads();

        // phase 2: z += s @ v
        #pragma unroll 2
        for (int m = 0; m < 128; m++) {
            float sv[8];
            #pragma unroll
            for (int i = 0; i < 8; i++) sv[i] = s_s[(tr + i) * 129 + m];
            float4 vv = *(const float4*)&kv[m * 68 + zc];
            #pragma unroll
            for (int i = 0; i < 8; i++) {
                zacc[i][0] = fmaf(sv[i], vv.x, zacc[i][0]);
                zacc[i][1] = fmaf(sv[i], vv.y, zacc[i][1]);
                zacc[i][2] = fmaf(sv[i], vv.z, zacc[i][2]);
                zacc[i][3] = fmaf(sv[i], vv.w, zacc[i][3]);
            }
        }
    }

    // epilogue: quantize z (16,8), write zc layout [b][n][h*64+e]
    const int b = bh / H_, h = bh - b * H_;
    #pragma unroll
    for (int i = 0; i < 8; i++) {
        int n = q0 + tr + i;
        float4 o;
        o.x = q16_8(zacc[i][0]);
        o.y = q16_8(zacc[i][1]);
        o.z = q16_8(zacc[i][2]);
        o.w = q16_8(zacc[i][3]);
        *(float4*)&g_z[((long)(b * N_ + n) * DIM_) + h * DH_ + zc] = o;
    }
}

// ---- kernel 4: output projection GEMM: out = q32_8(Z @ Wp^T + bp) ----
__global__ void __launch_bounds__(256) gemm_proj(float* __restrict__ out) {
    __shared__ float As[16][132];
    __shared__ float Bs[16][132];
    const int tid = threadIdx.x;
    const int m0 = blockIdx.y * 128;
    const int n0 = blockIdx.x * 128;
    const int tr = (tid >> 4) << 3;
    const int tc = (tid & 15) << 3;
    const int lr = tid >> 2;
    const int lc = (tid & 3) << 2;

    float acc[8][8];
    #pragma unroll
    for (int i = 0; i < 8; i++)
        #pragma unroll
        for (int j = 0; j < 8; j++) acc[i][j] = 0.f;

    const float* Ag = g_z  + (long)(m0 + lr) * DIM_ + lc;
    const float* Bg = g_wp + (long)(n0 + lr) * DIM_ + lc;

    for (int k0 = 0; k0 < DIM_; k0 += 16) {
        float4 a0 = *(const float4*)(Ag + k0);
        float4 a1 = *(const float4*)(Ag + 64 * DIM_ + k0);
        float4 b0 = *(const float4*)(Bg + k0);
        float4 b1 = *(const float4*)(Bg + 64 * DIM_ + k0);
        __syncthreads();
        As[lc+0][lr] = a0.x; As[lc+1][lr] = a0.y; As[lc+2][lr] = a0.z; As[lc+3][lr] = a0.w;
        As[lc+0][lr+64] = a1.x; As[lc+1][lr+64] = a1.y; As[lc+2][lr+64] = a1.z; As[lc+3][lr+64] = a1.w;
        Bs[lc+0][lr] = b0.x; Bs[lc+1][lr] = b0.y; Bs[lc+2][lr] = b0.z; Bs[lc+3][lr] = b0.w;
        Bs[lc+0][lr+64] = b1.x; Bs[lc+1][lr+64] = b1.y; Bs[lc+2][lr+64] = b1.z; Bs[lc+3][lr+64] = b1.w;
        __syncthreads();
        #pragma unroll
        for (int kk = 0; kk < 16; kk++) {
            float a[8], b[8];
            #pragma unroll
            for (int i = 0; i < 8; i++) a[i] = As[kk][tr + i];
            #pragma unroll
            for (int j = 0; j < 8; j++) b[j] = Bs[kk][tc + j];
            #pragma unroll
            for (int i = 0; i < 8; i++)
                #pragma unroll
                for (int j = 0; j < 8; j++) acc[i][j] = fmaf(a[i], b[j], acc[i][j]);
        }
    }
    #pragma unroll
    for (int j = 0; j < 8; j++) {
        int n = n0 + tc + j;
        float bias = g_bp[n];
        #pragma unroll
        for (int i = 0; i < 8; i++) {
            int m = m0 + tr + i;
            out[(long)m * DIM_ + n] = q32_8(acc[i][j] + bias);
        }
    }
}

extern "C" void kernel_launch(void* const* d_in, const int* in_sizes, int n_in,
                              void* d_out, int out_size) {
    const float* q_in = (const float*)d_in[0];
    const float* wqkv = (const float*)d_in[1];
    const float* bqkv = (const float*)d_in[2];
    const float* wp   = (const float*)d_in[3];
    const float* bp   = (const float*)d_in[4];
    float* out = (float*)d_out;

    const long total = (long)M1 * DIM_ + (long)NC1 * DIM_ + (long)DIM_ * DIM_ + NC1 + DIM_;
    quantize_all<<<(unsigned)((total + 255) / 256), 256>>>(q_in, wqkv, bqkv, wp, bp);

    dim3 g1(NC1 / 128, M1 / 128);   // (18, 32)
    gemm_qkv<<<g1, 256>>>();

    const int attn_smem = (64 * 128 + 8704 + 128 * 129) * 4;  // 133632 B
    cudaFuncSetAttribute(attn_kernel, cudaFuncAttributeMaxDynamicSharedMemorySize, attn_smem);
    dim3 g2(N_ / 128, B_ * H_);     // (16, 24)
    attn_kernel<<<g2, 256, attn_smem>>>();

    dim3 g3(DIM_ / 128, M1 / 128);  // (6, 32)
    gemm_proj<<<g3, 256>>>(out);
}

// round 3
// speedup vs baseline: 1.0583x; 1.0583x over previous
#include <cuda_runtime.h>
#include <cuda_fp16.h>
#include <cstdint>

#define B_   2
#define N_   2048
#define DIM_ 768
#define H_   12
#define DH_  64
#define M1   (B_*N_)     // 4096
#define NC1  (3*DIM_)    // 2304
#define KH2  768         // half2 (limb-pairs) per row
#define PITCHB 3072      // bytes per row of limb matrices (1536 halves)

// ---------------- device globals (allocation-free contract) ----------------
__device__ __half2 g_xl[(long)M1*KH2];    // x limbs [4096][768] (h,l)
__device__ __half2 g_w1[(long)NC1*KH2];   // wqkv limbs (h,l)
__device__ __half2 g_w2[(long)NC1*KH2];   // wqkv limbs swapped (l,h)
__device__ __half2 g_p1[(long)DIM_*KH2];  // wp limbs
__device__ __half2 g_p2[(long)DIM_*KH2];  // wp limbs swapped
__device__ __half2 g_zl[(long)M1*KH2];    // z limbs (from attention)
__device__ float   g_bq[NC1];
__device__ float   g_bp2[DIM_];
__device__ float   g_q[(long)M1*DIM_];    // [B,H,N,DH] fp32
__device__ float   g_k[(long)M1*DIM_];
__device__ float   g_v[(long)M1*DIM_];

// ---------------- quantizers ----------------
__device__ __forceinline__ float qround8(float x) {        // round-half-even to 2^-8, no clamp
    float t = __fmaf_rn(x, 256.f, 12582912.f);
    return (t - 12582912.f) * 0.00390625f;
}
__device__ __forceinline__ float q16_8c(float x) {         // with clamp (z saturates)
    float t = __fmaf_rn(x, 256.f, 12582912.f);
    float y = t - 12582912.f;
    y = fminf(fmaxf(y, -32768.f), 32767.f);
    return y * 0.00390625f;
}
__device__ __forceinline__ float q32_16(float x) {
    float t = __fmaf_rn(x, 65536.f, 12582912.f);
    return (t - 12582912.f) * 1.52587890625e-5f;
}

// ---------------- helpers ----------------
__device__ __forceinline__ uint32_t smem_u32(const void* p) {
    uint32_t a;
    asm("{ .reg .u64 t; cvta.to.shared.u64 t, %1; cvt.u32.u64 %0, t; }" : "=r"(a) : "l"(p));
    return a;
}
#define CP_ASYNC16(dst, src) \
    asm volatile("cp.async.cg.shared.global [%0], [%1], 16;" :: "r"(dst), "l"(src) : "memory")
#define CP_COMMIT() asm volatile("cp.async.commit_group;" ::: "memory")
#define CP_WAIT1()  asm volatile("cp.async.wait_group 1;" ::: "memory")
#define CP_WAIT0()  asm volatile("cp.async.wait_group 0;" ::: "memory")

__device__ __forceinline__ void ldm_x4(uint32_t* r, uint32_t addr) {
    asm volatile("ldmatrix.sync.aligned.m8n8.x4.shared.b16 {%0,%1,%2,%3}, [%4];"
        : "=r"(r[0]), "=r"(r[1]), "=r"(r[2]), "=r"(r[3]) : "r"(addr));
}
__device__ __forceinline__ void mma16816(float* d, const uint32_t* a, const uint32_t* b) {
    asm volatile("mma.sync.aligned.m16n8k16.row.col.f32.f16.f16.f32 "
        "{%0,%1,%2,%3}, {%4,%5,%6,%7}, {%8,%9}, {%0,%1,%2,%3};"
        : "+f"(d[0]), "+f"(d[1]), "+f"(d[2]), "+f"(d[3])
        : "r"(a[0]), "r"(a[1]), "r"(a[2]), "r"(a[3]), "r"(b[0]), "r"(b[1]));
}

// ---------------- kernel 1: quantize + limb-split everything ----------------
__global__ void prep_kernel(const float* __restrict__ x, const float* __restrict__ wqkv,
                            const float* __restrict__ bqkv, const float* __restrict__ wp,
                            const float* __restrict__ bp) {
    long i = (long)blockIdx.x * blockDim.x + threadIdx.x;
    const long NX = (long)M1 * DIM_;
    const long NW = (long)NC1 * DIM_;
    const long NP = (long)DIM_ * DIM_;
    if (i < NX) {
        float v = q32_16(x[i]);
        __half h = __float2half_rn(v);
        __half l = __float2half_rn(v - __half2float(h));
        g_xl[i] = __halves2half2(h, l);
        return;
    }
    i -= NX;
    if (i < NW) {
        float w = qround8(wqkv[i]);
        __half h = __float2half_rn(w);
        __half l = __float2half_rn(w - __half2float(h));
        g_w1[i] = __halves2half2(h, l);
        g_w2[i] = __halves2half2(l, h);
        return;
    }
    i -= NW;
    if (i < NP) {
        float w = qround8(wp[i]);
        __half h = __float2half_rn(w);
        __half l = __float2half_rn(w - __half2float(h));
        g_p1[i] = __halves2half2(h, l);
        g_p2[i] = __halves2half2(l, h);
        return;
    }
    i -= NP;
    if (i < NC1) { g_bq[i] = qround8(bqkv[i]); return; }
    i -= NC1;
    if (i < DIM_) g_bp2[i] = qround8(bp[i]);
}

// ---------------- HMMA GEMM core ----------------
// C[128m x 128n] = A(limbs) x B(limbs)^T over two passes (B1 then B2), K'=1536 halves each.
// smem: 2 stages x (A 16KB + B 16KB). Swizzle: 16B-chunk ^ (row%8).
#define STAGE_BYTES 32768
#define SWZ(row, colb) (((row) * 128) + ((colb) ^ (((row) & 7) * 16)))

struct AccTile { float a[2][8][4]; };

__device__ __forceinline__ void gemm_issue(uint32_t sA, uint32_t sB,
                                           const char* Ab, const char* Bb, int kbyte, int tid) {
    #pragma unroll
    for (int i = 0; i < 4; i++) {
        int idx = tid + i * 256;
        int row = idx >> 3;
        int c16 = (idx & 7) << 4;
        CP_ASYNC16(sA + SWZ(row, c16), Ab + (long)row * PITCHB + kbyte + c16);
    }
    #pragma unroll
    for (int i = 0; i < 4; i++) {
        int idx = tid + i * 256;
        int row = idx >> 3;
        int c16 = (idx & 7) << 4;
        CP_ASYNC16(sB + SWZ(row, c16), Bb + (long)row * PITCHB + kbyte + c16);
    }
    CP_COMMIT();
}

__device__ __forceinline__ void gemm_compute(uint32_t sA, uint32_t sB, AccTile& acc,
                                             int wm, int wn, int lane) {
    const int arow_l = (lane & 7) + ((lane >> 3) & 1) * 8;
    const int achk   = (lane >> 4) * 16;
    const int brow_l = (lane & 7) + (lane >> 4) * 8;
    const int bchk   = ((lane >> 3) & 1) * 16;
    #pragma unroll
    for (int s = 0; s < 4; s++) {
        uint32_t a[2][4];
        #pragma unroll
        for (int f = 0; f < 2; f++) {
            int row = wm * 32 + f * 16 + arow_l;
            ldm_x4(a[f], sA + SWZ(row, s * 32 + achk));
        }
        #pragma unroll
        for (int jp = 0; jp < 4; jp++) {
            uint32_t b[4];
            int row = wn * 64 + jp * 16 + brow_l;
            ldm_x4(b, sB + SWZ(row, s * 32 + bchk));
            #pragma unroll
            for (int f = 0; f < 2; f++) {
                mma16816(acc.a[f][jp * 2 + 0], a[f], b + 0);
                mma16816(acc.a[f][jp * 2 + 1], a[f], b + 2);
            }
        }
    }
}

__device__ __forceinline__ void gemm_main(const char* Ab, const char* B1b, const char* B2b,
                                          AccTile& acc, char* smem, int tid) {
    uint32_t sb = smem_u32(smem);
    const int wid = tid >> 5, lane = tid & 31;
    const int wm = wid & 3, wn = wid >> 2;
    #pragma unroll
    for (int f = 0; f < 2; f++)
        #pragma unroll
        for (int j = 0; j < 8; j++)
            #pragma unroll
            for (int e = 0; e < 4; e++) acc.a[f][j][e] = 0.f;

    const int G = 48;
    gemm_issue(sb, sb + 16384, Ab, B1b, 0, tid);
    #pragma unroll 1
    for (int g = 0; g < G; g++) {
        if (g + 1 < G) {
            int pass = (g + 1) >= 24;
            int kb = ((g + 1) - 24 * pass) * 128;
            uint32_t st = ((g + 1) & 1) * STAGE_BYTES;
            gemm_issue(sb + st, sb + st + 16384, Ab, pass ? B2b : B1b, kb, tid);
            CP_WAIT1();
        } else {
            CP_WAIT0();
        }
        __syncthreads();
        uint32_t st = (g & 1) * STAGE_BYTES;
        gemm_compute(sb + st, sb + st + 16384, acc, wm, wn, lane);
        __syncthreads();
    }
}

// ---------------- kernel 2: QKV projection (HMMA) ----------------
__global__ void __launch_bounds__(256, 1) gemm_qkv_tc() {
    extern __shared__ char smem[];
    const int tid = threadIdx.x;
    const int m0 = blockIdx.y * 128;
    const int n0 = blockIdx.x * 128;
    AccTile acc;
    gemm_main((const char*)g_xl + (long)m0 * PITCHB,
              (const char*)g_w1 + (long)n0 * PITCHB,
              (const char*)g_w2 + (long)n0 * PITCHB, acc, smem, tid);

    const int wid = tid >> 5, lane = tid & 31;
    const int wm = wid & 3, wn = wid >> 2;
    const int rb = m0 + wm * 32 + (lane >> 2);
    const int cb = n0 + wn * 64 + (lane & 3) * 2;
    #pragma unroll
    for (int f = 0; f < 2; f++) {
        #pragma unroll
        for (int j = 0; j < 8; j++) {
            #pragma unroll
            for (int cs = 0; cs < 2; cs++) {
                int n = cb + j * 8 + cs;
                float bias = g_bq[n];
                int h = n / 192;
                int rr = n - h * 192;
                int seg = rr >> 6, e = rr & 63;
                float* dst = (seg == 0) ? g_q : ((seg == 1) ? g_k : g_v);
                #pragma unroll
                for (int rs = 0; rs < 2; rs++) {
                    int m = rb + f * 16 + rs * 8;
                    int bi = m >> 11, nr = m & 2047;
                    dst[((long)((bi * H_ + h) * N_ + nr)) * DH_ + e] =
                        qround8(acc.a[f][j][rs * 2 + cs] + bias);
                }
            }
        }
    }
}

// ---------------- kernel 4: output projection (HMMA) ----------------
__global__ void __launch_bounds__(256, 1) gemm_proj_tc(float* __restrict__ out) {
    extern __shared__ char smem[];
    const int tid = threadIdx.x;
    const int m0 = blockIdx.y * 128;
    const int n0 = blockIdx.x * 128;
    AccTile acc;
    gemm_main((const char*)g_zl + (long)m0 * PITCHB,
              (const char*)g_p1 + (long)n0 * PITCHB,
              (const char*)g_p2 + (long)n0 * PITCHB, acc, smem, tid);

    const int wid = tid >> 5, lane = tid & 31;
    const int wm = wid & 3, wn = wid >> 2;
    const int rb = m0 + wm * 32 + (lane >> 2);
    const int cb = n0 + wn * 64 + (lane & 3) * 2;
    #pragma unroll
    for (int f = 0; f < 2; f++) {
        #pragma unroll
        for (int j = 0; j < 8; j++) {
            #pragma unroll
            for (int cs = 0; cs < 2; cs++) {
                int n = cb + j * 8 + cs;
                float bias = g_bp2[n];
                #pragma unroll
                for (int rs = 0; rs < 2; rs++) {
                    int m = rb + f * 16 + rs * 8;
                    out[(long)m * DIM_ + n] = qround8(acc.a[f][j][rs * 2 + cs] + bias);
                }
            }
        }
    }
}

// ---------------- kernel 3: fused attention (FFMA) ----------------
__global__ void __launch_bounds__(256) attn_kernel() {
    extern __shared__ float sm[];
    float* q_s = sm;               // [64][128] transposed
    float* kv  = sm + 64 * 128;    // k phase: [64][128]; v phase: [128][68]
    float* s_s = kv + 8704;        // [128][129]

    const int tid = threadIdx.x;
    const int bh = blockIdx.y;
    const int q0 = blockIdx.x * 128;
    const float* qb = g_q + (long)bh * N_ * DH_;
    const float* kb = g_k + (long)bh * N_ * DH_;
    const float* vb = g_v + (long)bh * N_ * DH_;

    const int f4 = (tid & 15) << 2;
    const int r0 = tid >> 4;

    #pragma unroll
    for (int p = 0; p < 8; p++) {
        int r = r0 + p * 16;
        float4 v4 = *(const float4*)(qb + (long)(q0 + r) * DH_ + f4);
        q_s[(f4 + 0) * 128 + r] = v4.x;
        q_s[(f4 + 1) * 128 + r] = v4.y;
        q_s[(f4 + 2) * 128 + r] = v4.z;
        q_s[(f4 + 3) * 128 + r] = v4.w;
    }

    const int tr = (tid >> 4) << 3;
    const int tc = (tid & 15) << 3;
    const int zc = (tid & 15) << 2;

    float zacc[8][4];
    #pragma unroll
    for (int i = 0; i < 8; i++)
        #pragma unroll
        for (int j = 0; j < 4; j++) zacc[i][j] = 0.f;

    for (int kt = 0; kt < 16; kt++) {
        const int kbase = kt * 128;
        __syncthreads();
        #pragma unroll
        for (int p = 0; p < 8; p++) {
            int r = r0 + p * 16;
            float4 v4 = *(const float4*)(kb + (long)(kbase + r) * DH_ + f4);
            kv[(f4 + 0) * 128 + r] = v4.x;
            kv[(f4 + 1) * 128 + r] = v4.y;
            kv[(f4 + 2) * 128 + r] = v4.z;
            kv[(f4 + 3) * 128 + r] = v4.w;
        }
        __syncthreads();

        float sacc[8][8];
        #pragma unroll
        for (int i = 0; i < 8; i++)
            #pragma unroll
            for (int j = 0; j < 8; j++) sacc[i][j] = 0.f;
        #pragma unroll 4
        for (int e = 0; e < 64; e++) {
            float a[8], b[8];
            #pragma unroll
            for (int i = 0; i < 8; i++) a[i] = q_s[e * 128 + tr + i];
            #pragma unroll
            for (int j = 0; j < 8; j++) b[j] = kv[e * 128 + tc + j];
            #pragma unroll
            for (int i = 0; i < 8; i++)
                #pragma unroll
                for (int j = 0; j < 8; j++) sacc[i][j] = fmaf(a[i], b[j], sacc[i][j]);
        }
        #pragma unroll
        for (int i = 0; i < 8; i++)
            #pragma unroll
            for (int j = 0; j < 8; j++)
                s_s[(tr + i) * 129 + (tc + j)] = qround8(sacc[i][j]);
        __syncthreads();

        #pragma unroll
        for (int p = 0; p < 8; p++) {
            int r = r0 + p * 16;
            float4 v4 = *(const float4*)(vb + (long)(kbase + r) * DH_ + f4);
            *(float4*)&kv[r * 68 + f4] = v4;
        }
        __syncthreads();

        #pragma unroll 2
        for (int m = 0; m < 128; m++) {
            float sv[8];
            #pragma unroll
            for (int i = 0; i < 8; i++) sv[i] = s_s[(tr + i) * 129 + m];
            float4 vv = *(const float4*)&kv[m * 68 + zc];
            #pragma unroll
            for (int i = 0; i < 8; i++) {
                zacc[i][0] = fmaf(sv[i], vv.x, zacc[i][0]);
                zacc[i][1] = fmaf(sv[i], vv.y, zacc[i][1]);
                zacc[i][2] = fmaf(sv[i], vv.z, zacc[i][2]);
                zacc[i][3] = fmaf(sv[i], vv.w, zacc[i][3]);
            }
        }
    }

    // epilogue: quantize z (16,8) with clamp, split to fp16 limbs for proj GEMM
    const int b = bh / H_, h = bh - b * H_;
    #pragma unroll
    for (int i = 0; i < 8; i++) {
        int n = q0 + tr + i;
        uint4 o;
        uint32_t* po = (uint32_t*)&o;
        #pragma unroll
        for (int j = 0; j < 4; j++) {
            float zq = q16_8c(zacc[i][j]);
            __half hh = __float2half_rn(zq);
            __half ll = __float2half_rn(zq - __half2float(hh));
            __half2 pk = __halves2half2(hh, ll);
            po[j] = *(uint32_t*)&pk;
        }
        *(uint4*)((uint32_t*)g_zl + (long)(b * N_ + n) * KH2 + (h * DH_ + zc)) = o;
    }
}

// ---------------- launch ----------------
extern "C" void kernel_launch(void* const* d_in, const int* in_sizes, int n_in,
                              void* d_out, int out_size) {
    const float* q_in = (const float*)d_in[0];
    const float* wqkv = (const float*)d_in[1];
    const float* bqkv = (const float*)d_in[2];
    const float* wp   = (const float*)d_in[3];
    const float* bp   = (const float*)d_in[4];
    float* out = (float*)d_out;

    const long total = (long)M1 * DIM_ + (long)NC1 * DIM_ + (long)DIM_ * DIM_ + NC1 + DIM_;
    prep_kernel<<<(unsigned)((total + 255) / 256), 256>>>(q_in, wqkv, bqkv, wp, bp);

    const int gemm_smem = 2 * STAGE_BYTES;   // 65536
    cudaFuncSetAttribute(gemm_qkv_tc, cudaFuncAttributeMaxDynamicSharedMemorySize, gemm_smem);
    gemm_qkv_tc<<<dim3(NC1 / 128, M1 / 128), 256, gemm_smem>>>();   // (18, 32)

    const int attn_smem = (64 * 128 + 8704 + 128 * 129) * 4;        // 133632 B
    cudaFuncSetAttribute(attn_kernel, cudaFuncAttributeMaxDynamicSharedMemorySize, attn_smem);
    attn_kernel<<<dim3(N_ / 128, B_ * H_), 256, attn_smem>>>();     // (16, 24)

    cudaFuncSetAttribute(gemm_proj_tc, cudaFuncAttributeMaxDynamicSharedMemorySize, gemm_smem);
    gemm_proj_tc<<<dim3(DIM_ / 128, M1 / 128), 256, gemm_smem>>>(out);  // (6, 32)
}

// round 4
// speedup vs baseline: 2.4351x; 2.3010x over previous
#include <cuda_runtime.h>
#include <cuda_fp16.h>
#include <cstdint>

#define B_   2
#define N_   2048
#define DIM_ 768
#define H_   12
#define DH_  64
#define M1   (B_*N_)     // 4096
#define NC1  (3*DIM_)    // 2304
#define KH2  768         // half2 limb-pairs per GEMM row
#define PITCHB 3072      // bytes per GEMM limb row

// ---------------- device globals ----------------
__device__ uint32_t g_xl[(long)M1*KH2];      // x limbs (h,l)
__device__ uint32_t g_w1[(long)NC1*KH2];     // wqkv limbs (h,l)
__device__ uint32_t g_w2[(long)NC1*KH2];     // wqkv limbs (l,h)
__device__ uint32_t g_p1[(long)DIM_*KH2];    // wp limbs
__device__ uint32_t g_p2[(long)DIM_*KH2];
__device__ uint32_t g_zl[(long)M1*KH2];      // z limbs (attention output)
__device__ uint32_t g_ql[(long)B_*H_*N_*DH_];        // q limbs [bh][n][64]
__device__ uint32_t g_k12[(long)B_*H_*N_*2*DH_];     // k limbs [bh][m][128]: (kh,kl)x64 | (kl,kh)x64
__device__ uint32_t g_vt[(long)B_*H_*DH_*N_];        // v^T limbs [bh][e][m] (vh,vl)
__device__ uint32_t g_vt2[(long)B_*H_*DH_*N_];       // swapped (vl,vh)
__device__ float    g_bq[NC1];
__device__ float    g_bp2[DIM_];

// ---------------- quantizers ----------------
__device__ __forceinline__ float qround8(float x) {        // round-half-even to 2^-8
    float t = __fmaf_rn(x, 256.f, 12582912.f);
    return (t - 12582912.f) * 0.00390625f;
}
__device__ __forceinline__ float q16_8c(float x) {         // with clamp (z saturates)
    float t = __fmaf_rn(x, 256.f, 12582912.f);
    float y = t - 12582912.f;
    y = fminf(fmaxf(y, -32768.f), 32767.f);
    return y * 0.00390625f;
}
__device__ __forceinline__ float q32_16(float x) {
    float t = __fmaf_rn(x, 65536.f, 12582912.f);
    return (t - 12582912.f) * 1.52587890625e-5f;
}
__device__ __forceinline__ uint32_t packu32(__half a, __half b) {
    __half2 t = __halves2half2(a, b);
    return *(uint32_t*)&t;
}

// ---------------- PTX helpers ----------------
__device__ __forceinline__ uint32_t smem_u32(const void* p) {
    uint32_t a;
    asm("{ .reg .u64 t; cvta.to.shared.u64 t, %1; cvt.u32.u64 %0, t; }" : "=r"(a) : "l"(p));
    return a;
}
#define CP_ASYNC16(dst, src) \
    asm volatile("cp.async.cg.shared.global [%0], [%1], 16;" :: "r"(dst), "l"(src) : "memory")
#define CP_COMMIT() asm volatile("cp.async.commit_group;" ::: "memory")
#define CP_WAIT(n)  asm volatile("cp.async.wait_group %0;" :: "n"(n) : "memory")

__device__ __forceinline__ void ldm_x4(uint32_t* r, uint32_t addr) {
    asm volatile("ldmatrix.sync.aligned.m8n8.x4.shared.b16 {%0,%1,%2,%3}, [%4];"
        : "=r"(r[0]), "=r"(r[1]), "=r"(r[2]), "=r"(r[3]) : "r"(addr));
}
__device__ __forceinline__ void mma16816(float* d, const uint32_t* a, const uint32_t* b) {
    asm volatile("mma.sync.aligned.m16n8k16.row.col.f32.f16.f16.f32 "
        "{%0,%1,%2,%3}, {%4,%5,%6,%7}, {%8,%9}, {%0,%1,%2,%3};"
        : "+f"(d[0]), "+f"(d[1]), "+f"(d[2]), "+f"(d[3])
        : "r"(a[0]), "r"(a[1]), "r"(a[2]), "r"(a[3]), "r"(b[0]), "r"(b[1]));
}

// swizzle: XOR 16B-chunk id with row%8 within a 128B group
#define SWP(pitch, row, colb) ((uint32_t)((row)*(pitch) + (((colb)) ^ (((row)&7)<<4))))
#define SWZ(row, colb) SWP(128, row, colb)

// ---------------- kernel 1: quantize + limb-split inputs ----------------
__global__ void prep_kernel(const float* __restrict__ x, const float* __restrict__ wqkv,
                            const float* __restrict__ bqkv, const float* __restrict__ wp,
                            const float* __restrict__ bp) {
    long i = (long)blockIdx.x * blockDim.x + threadIdx.x;
    const long NX = (long)M1 * DIM_;
    const long NW = (long)NC1 * DIM_;
    const long NP = (long)DIM_ * DIM_;
    if (i < NX) {
        float v = q32_16(x[i]);
        __half h = __float2half_rn(v);
        __half l = __float2half_rn(v - __half2float(h));
        g_xl[i] = packu32(h, l);
        return;
    }
    i -= NX;
    if (i < NW) {
        float w = qround8(wqkv[i]);
        __half h = __float2half_rn(w);
        __half l = __float2half_rn(w - __half2float(h));
        g_w1[i] = packu32(h, l);
        g_w2[i] = packu32(l, h);
        return;
    }
    i -= NW;
    if (i < NP) {
        float w = qround8(wp[i]);
        __half h = __float2half_rn(w);
        __half l = __float2half_rn(w - __half2float(h));
        g_p1[i] = packu32(h, l);
        g_p2[i] = packu32(l, h);
        return;
    }
    i -= NP;
    if (i < NC1) { g_bq[i] = qround8(bqkv[i]); return; }
    i -= NC1;
    if (i < DIM_) g_bp2[i] = qround8(bp[i]);
}

// ---------------- GEMM v2: dual-B single pass, 3-stage, 1 sync/chunk ----------------
// Stage: A 16KB | B1 16KB | B2 16KB = 48KB. 24 chunks of 128B (64 halves).
#define GSTG 49152
struct AccTile { float a[2][8][4]; };

__device__ __forceinline__ void gemm_issue2(uint32_t st, const char* Ab, const char* B1b,
                                            const char* B2b, int kbyte, int tid) {
    #pragma unroll
    for (int i = 0; i < 4; i++) {
        int idx = tid + i * 256;
        int row = idx >> 3, c16 = (idx & 7) << 4;
        CP_ASYNC16(st + SWZ(row, c16), Ab + (long)row * PITCHB + kbyte + c16);
    }
    #pragma unroll
    for (int i = 0; i < 4; i++) {
        int idx = tid + i * 256;
        int row = idx >> 3, c16 = (idx & 7) << 4;
        CP_ASYNC16(st + 16384 + SWZ(row, c16), B1b + (long)row * PITCHB + kbyte + c16);
    }
    #pragma unroll
    for (int i = 0; i < 4; i++) {
        int idx = tid + i * 256;
        int row = idx >> 3, c16 = (idx & 7) << 4;
        CP_ASYNC16(st + 32768 + SWZ(row, c16), B2b + (long)row * PITCHB + kbyte + c16);
    }
    CP_COMMIT();
}

__device__ __forceinline__ void gemm_compute2(uint32_t st, AccTile& acc, int wm, int wn, int lane) {
    const int arow_l = (lane & 7) + ((lane >> 3) & 1) * 8;
    const int achk   = (lane >> 4) * 16;
    const int brow_l = (lane & 7) + (lane >> 4) * 8;
    const int bchk   = ((lane >> 3) & 1) * 16;
    #pragma unroll
    for (int kk = 0; kk < 4; kk++) {
        uint32_t a[2][4];
        #pragma unroll
        for (int f = 0; f < 2; f++)
            ldm_x4(a[f], st + SWZ(wm * 32 + f * 16 + arow_l, kk * 32 + achk));
        #pragma unroll
        for (int half = 0; half < 2; half++) {
            uint32_t base = st + 16384 + half * 16384;
            #pragma unroll
            for (int g = 0; g < 4; g++) {
                uint32_t b4[4];
                ldm_x4(b4, base + SWZ(wn * 64 + g * 16 + brow_l, kk * 32 + bchk));
                #pragma unroll
                for (int f = 0; f < 2; f++) {
                    mma16816(acc.a[f][g * 2 + 0], a[f], b4 + 0);
                    mma16816(acc.a[f][g * 2 + 1], a[f], b4 + 2);
                }
            }
        }
    }
}

__device__ __forceinline__ void gemm_main2(const char* Ab, const char* B1b, const char* B2b,
                                           AccTile& acc, char* smem, int tid) {
    uint32_t sb = smem_u32(smem);
    const int lane = tid & 31, wid = tid >> 5;
    const int wm = wid & 3, wn = wid >> 2;
    #pragma unroll
    for (int f = 0; f < 2; f++)
        #pragma unroll
        for (int j = 0; j < 8; j++)
            #pragma unroll
            for (int e = 0; e < 4; e++) acc.a[f][j][e] = 0.f;

    gemm_issue2(sb + 0 * GSTG, Ab, B1b, B2b, 0, tid);
    gemm_issue2(sb + 1 * GSTG, Ab, B1b, B2b, 128, tid);
    #pragma unroll 1
    for (int g = 0; g < 24; g++) {
        if (g + 2 < 24) { CP_WAIT(1); } else { CP_WAIT(0); }
        __syncthreads();
        if (g + 2 < 24)
            gemm_issue2(sb + ((g + 2) % 3) * GSTG, Ab, B1b, B2b, (g + 2) * 128, tid);
        gemm_compute2(sb + (g % 3) * GSTG, acc, wm, wn, lane);
    }
}

// ---------------- kernel 2: QKV projection (HMMA) + attention-layout epilogue ----------------
__global__ void __launch_bounds__(256, 1) gemm_qkv_tc() {
    extern __shared__ char smem[];
    const int tid = threadIdx.x;
    const int m0 = blockIdx.y * 128;
    const int n0 = blockIdx.x * 128;
    AccTile acc;
    gemm_main2((const char*)g_xl + (long)m0 * PITCHB,
               (const char*)g_w1 + (long)n0 * PITCHB,
               (const char*)g_w2 + (long)n0 * PITCHB, acc, smem, tid);

    const int wid = tid >> 5, lane = tid & 31;
    const int wm = wid & 3, wn = wid >> 2;
    const int rb = m0 + wm * 32 + (lane >> 2);
    const int cb = n0 + wn * 64 + (lane & 3) * 2;
    #pragma unroll
    for (int f = 0; f < 2; f++) {
        #pragma unroll
        for (int j = 0; j < 8; j++) {
            #pragma unroll
            for (int cs = 0; cs < 2; cs++) {
                int n = cb + j * 8 + cs;
                float bias = g_bq[n];
                int h = n / 192;
                int rr = n - h * 192;
                int seg = rr >> 6, e = rr & 63;
                #pragma unroll
                for (int rs = 0; rs < 2; rs++) {
                    int m = rb + f * 16 + rs * 8;
                    int bi = m >> 11, nr = m & 2047;
                    long bh = bi * H_ + h;
                    float v = qround8(acc.a[f][j][rs * 2 + cs] + bias);
                    __half hh = __float2half_rn(v);
                    __half ll = __float2half_rn(v - __half2float(hh));
                    if (seg == 0) {
                        g_ql[(bh * N_ + nr) * DH_ + e] = packu32(hh, ll);
                    } else if (seg == 1) {
                        long base = (bh * N_ + nr) * (2 * DH_);
                        g_k12[base + e]       = packu32(hh, ll);
                        g_k12[base + DH_ + e] = packu32(ll, hh);
                    } else {
                        long base = (bh * DH_ + e) * N_ + nr;
                        g_vt[base]  = packu32(hh, ll);
                        g_vt2[base] = packu32(ll, hh);
                    }
                }
            }
        }
    }
}

// ---------------- kernel 4: output projection (HMMA) ----------------
__global__ void __launch_bounds__(256, 1) gemm_proj_tc(float* __restrict__ out) {
    extern __shared__ char smem[];
    const int tid = threadIdx.x;
    const int m0 = blockIdx.y * 128;
    const int n0 = blockIdx.x * 128;
    AccTile acc;
    gemm_main2((const char*)g_zl + (long)m0 * PITCHB,
               (const char*)g_p1 + (long)n0 * PITCHB,
               (const char*)g_p2 + (long)n0 * PITCHB, acc, smem, tid);

    const int wid = tid >> 5, lane = tid & 31;
    const int wm = wid & 3, wn = wid >> 2;
    const int rb = m0 + wm * 32 + (lane >> 2);
    const int cb = n0 + wn * 64 + (lane & 3) * 2;
    #pragma unroll
    for (int f = 0; f < 2; f++) {
        #pragma unroll
        for (int j = 0; j < 8; j++) {
            #pragma unroll
            for (int cs = 0; cs < 2; cs++) {
                int n = cb + j * 8 + cs;
                float bias = g_bp2[n];
                #pragma unroll
                for (int rs = 0; rs < 2; rs++) {
                    int m = rb + f * 16 + rs * 8;
                    out[(long)m * DIM_ + n] = qround8(acc.a[f][j][rs * 2 + cs] + bias);
                }
            }
        }
    }
}

// ---------------- kernel 3: HMMA limb flash-attention ----------------
// smem: Q [128x256B] | K 2 stages [64x512B] | Vt 2 stages [2 bufs x 64x256B] | S [128x256B]
#define AOQ  0u
#define AOK  32768u
#define AOV  98304u
#define AOS  163840u
#define ATTN_SMEM 196608

__device__ __forceinline__ void attn_issue_kv(uint32_t sK_st, uint32_t sV_st,
        const char* kbase, const char* v0base, const char* v1base, int kb, int tid) {
    #pragma unroll
    for (int i = 0; i < 8; i++) {
        int idx = tid + i * 256;
        int row = idx >> 5, c16 = (idx & 31) << 4;
        CP_ASYNC16(sK_st + SWP(512, row, c16), kbase + (long)(kb + row) * 512 + c16);
    }
    #pragma unroll
    for (int i = 0; i < 8; i++) {
        int idx = tid + i * 256;
        int buf = idx >> 10;
        int row = (idx >> 4) & 63;
        int c16 = (idx & 15) << 4;
        const char* vb = buf ? v1base : v0base;
        CP_ASYNC16(sV_st + buf * 16384 + SWP(256, row, c16),
                   vb + (long)row * (N_ * 4) + kb * 4 + c16);
    }
    CP_COMMIT();
}

__global__ void __launch_bounds__(256, 1) attn_tc_kernel() {
    extern __shared__ char smem[];
    const uint32_t sb = smem_u32(smem);
    const int tid = threadIdx.x;
    const int lane = tid & 31, wid = tid >> 5;
    const int wm = wid & 3, wn = wid >> 2;
    const int bh = blockIdx.y;
    const int q0 = blockIdx.x * 128;

    const char* qbase  = (const char*)(g_ql  + (long)bh * N_ * DH_) + (long)q0 * 256;
    const char* kbase  = (const char*)(g_k12 + (long)bh * N_ * 2 * DH_);
    const char* v0base = (const char*)(g_vt  + (long)bh * DH_ * N_);
    const char* v1base = (const char*)(g_vt2 + (long)bh * DH_ * N_);

    // prologue: load Q tile + first K/Vt stage (one group)
    #pragma unroll
    for (int i = 0; i < 8; i++) {
        int idx = tid + i * 256;
        int row = idx >> 4, c16 = (idx & 15) << 4;
        CP_ASYNC16(sb + AOQ + SWP(256, row, c16), qbase + (long)row * 256 + c16);
    }
    attn_issue_kv(sb + AOK, sb + AOV, kbase, v0base, v1base, 0, tid);

    const int arow_l = (lane & 7) + ((lane >> 3) & 1) * 8;
    const int achk   = (lane >> 4) * 16;
    const int brow_l = (lane & 7) + (lane >> 4) * 8;
    const int bchk   = ((lane >> 3) & 1) * 16;
    const int qr     = lane >> 2;       // c-frag row within 8
    const int qc     = (lane & 3) * 2;  // c-frag col pair

    float zacc[2][4][4];
    #pragma unroll
    for (int f = 0; f < 2; f++)
        #pragma unroll
        for (int j = 0; j < 4; j++)
            #pragma unroll
            for (int e = 0; e < 4; e++) zacc[f][j][e] = 0.f;

    #pragma unroll 1
    for (int it = 0; it < 32; it++) {
        const uint32_t sK = sb + AOK + (uint32_t)(it & 1) * 32768u;
        const uint32_t sV = sb + AOV + (uint32_t)(it & 1) * 32768u;
        CP_WAIT(0);
        __syncthreads();
        if (it + 1 < 32)
            attn_issue_kv(sb + AOK + (uint32_t)((it + 1) & 1) * 32768u,
                          sb + AOV + (uint32_t)((it + 1) & 1) * 32768u,
                          kbase, v0base, v1base, (it + 1) * 64, tid);

        // ---- phase 1: s[128x64] = q x k^T (K = 256 limb-halves) ----
        float sacc[2][4][4];
        #pragma unroll
        for (int f = 0; f < 2; f++)
            #pragma unroll
            for (int j = 0; j < 4; j++)
                #pragma unroll
                for (int e = 0; e < 4; e++) sacc[f][j][e] = 0.f;
        #pragma unroll
        for (int kk = 0; kk < 16; kk++) {
            int aoff = (kk & 7) * 32;
            uint32_t a[2][4];
            #pragma unroll
            for (int f = 0; f < 2; f++)
                ldm_x4(a[f], sb + AOQ + SWP(256, wm * 32 + f * 16 + arow_l, aoff + achk));
            #pragma unroll
            for (int g = 0; g < 2; g++) {
                uint32_t b4[4];
                ldm_x4(b4, sK + SWP(512, wn * 32 + g * 16 + brow_l, kk * 32 + bchk));
                #pragma unroll
                for (int f = 0; f < 2; f++) {
                    mma16816(sacc[f][g * 2 + 0], a[f], b4 + 0);
                    mma16816(sacc[f][g * 2 + 1], a[f], b4 + 2);
                }
            }
        }
        // quantize s, split limbs, store interleaved (sh,sl) into sS
        #pragma unroll
        for (int f = 0; f < 2; f++) {
            #pragma unroll
            for (int jn = 0; jn < 4; jn++) {
                #pragma unroll
                for (int rs = 0; rs < 2; rs++) {
                    #pragma unroll
                    for (int cs = 0; cs < 2; cs++) {
                        int row = wm * 32 + f * 16 + qr + rs * 8;
                        int col = wn * 32 + jn * 8 + qc + cs;
                        float sq = qround8(sacc[f][jn][rs * 2 + cs]);
                        __half hh = __float2half_rn(sq);
                        __half ll = __float2half_rn(sq - __half2float(hh));
                        *(uint32_t*)(smem + AOS + (uint32_t)(row * 256 + ((col * 4) ^ ((row & 7) << 4)))) =
                            packu32(hh, ll);
                    }
                }
            }
        }
        __syncthreads();

        // ---- phase 2: z += s x v (K = 128 limb-halves, both vt buffers) ----
        #pragma unroll
        for (int kk = 0; kk < 8; kk++) {
            uint32_t a[2][4];
            #pragma unroll
            for (int f = 0; f < 2; f++)
                ldm_x4(a[f], sb + AOS + SWP(256, wm * 32 + f * 16 + arow_l, kk * 32 + achk));
            #pragma unroll
            for (int buf = 0; buf < 2; buf++) {
                uint32_t base = sV + buf * 16384;
                #pragma unroll
                for (int g = 0; g < 2; g++) {
                    uint32_t b4[4];
                    ldm_x4(b4, base + SWP(256, wn * 32 + g * 16 + brow_l, kk * 32 + bchk));
                    #pragma unroll
                    for (int f = 0; f < 2; f++) {
                        mma16816(zacc[f][g * 2 + 0], a[f], b4 + 0);
                        mma16816(zacc[f][g * 2 + 1], a[f], b4 + 2);
                    }
                }
            }
        }
    }

    // epilogue: quantize z (clamped), limb-split, write zc layout for proj GEMM
    const int b = bh / H_, h = bh - b * H_;
    #pragma unroll
    for (int f = 0; f < 2; f++) {
        #pragma unroll
        for (int jn = 0; jn < 4; jn++) {
            #pragma unroll
            for (int rs = 0; rs < 2; rs++) {
                #pragma unroll
                for (int cs = 0; cs < 2; cs++) {
                    int n = q0 + wm * 32 + f * 16 + qr + rs * 8;
                    int e = wn * 32 + jn * 8 + qc + cs;
                    float zq = q16_8c(zacc[f][jn][rs * 2 + cs]);
                    __half hh = __float2half_rn(zq);
                    __half ll = __float2half_rn(zq - __half2float(hh));
                    g_zl[((long)(b * N_ + n)) * KH2 + h * DH_ + e] = packu32(hh, ll);
                }
            }
        }
    }
}

// ---------------- launch ----------------
extern "C" void kernel_launch(void* const* d_in, const int* in_sizes, int n_in,
                              void* d_out, int out_size) {
    const float* q_in = (const float*)d_in[0];
    const float* wqkv = (const float*)d_in[1];
    const float* bqkv = (const float*)d_in[2];
    const float* wp   = (const float*)d_in[3];
    const float* bp   = (const float*)d_in[4];
    float* out = (float*)d_out;

    const long total = (long)M1 * DIM_ + (long)NC1 * DIM_ + (long)DIM_ * DIM_ + NC1 + DIM_;
    prep_kernel<<<(unsigned)((total + 255) / 256), 256>>>(q_in, wqkv, bqkv, wp, bp);

    const int gemm_smem = 3 * GSTG;   // 147456
    cudaFuncSetAttribute(gemm_qkv_tc, cudaFuncAttributeMaxDynamicSharedMemorySize, gemm_smem);
    gemm_qkv_tc<<<dim3(NC1 / 128, M1 / 128), 256, gemm_smem>>>();       // (18, 32)

    cudaFuncSetAttribute(attn_tc_kernel, cudaFuncAttributeMaxDynamicSharedMemorySize, ATTN_SMEM);
    attn_tc_kernel<<<dim3(N_ / 128, B_ * H_), 256, ATTN_SMEM>>>();      // (16, 24)

    cudaFuncSetAttribute(gemm_proj_tc, cudaFuncAttributeMaxDynamicSharedMemorySize, gemm_smem);
    gemm_proj_tc<<<dim3(DIM_ / 128, M1 / 128), 256, gemm_smem>>>(out);  // (6, 32)
}